// round 4
// baseline (speedup 1.0000x reference)
#include <cuda_runtime.h>
#include <cstdint>
#include <cfloat>

// Problem constants
#define NB   128
#define NP   8732
#define NC   21
#define TOPK 200
#define NT   1024

// Scratch (device globals: no allocation allowed)
__device__ float         g_scores[NB * NP];
__device__ float4        g_boxes [NB * NP];
__device__ unsigned char g_cls   [NB * NP];

// ---------------------------------------------------------------------------
// Stage 1: softmax-max + class argmax + box decode, one thread per (b, p) row
// ---------------------------------------------------------------------------
__global__ void preprocess_kernel(const float* __restrict__ loc,
                                  const float* __restrict__ conf,
                                  const float* __restrict__ prior) {
    int row = blockIdx.x * blockDim.x + threadIdx.x;
    if (row >= NB * NP) return;

    const float* cp = conf + (size_t)row * NC;
    float c[NC];
#pragma unroll
    for (int i = 0; i < NC; i++) c[i] = cp[i];

    float m = c[0];
#pragma unroll
    for (int i = 1; i < NC; i++) m = fmaxf(m, c[i]);

    float sum = 0.0f;
#pragma unroll
    for (int i = 0; i < NC; i++) sum += expf(c[i] - m);

    float bm = c[1]; int bc = 1;
#pragma unroll
    for (int i = 2; i < NC; i++) {
        if (c[i] > bm) { bm = c[i]; bc = i; }
    }
    float score = expf(bm - m) / sum;
    float ms = (score > 0.01f) ? score : -1.0f;

    int p = row % NP;
    float4 l  = ((const float4*)loc)[row];
    float4 pr = ((const float4*)prior)[p];
    float cx = pr.x + l.x * 0.1f * pr.z;
    float cy = pr.y + l.y * 0.1f * pr.w;
    float w  = pr.z * expf(l.z * 0.2f);
    float h  = pr.w * expf(l.w * 0.2f);

    g_scores[row] = ms;
    g_boxes [row] = make_float4(cx - w * 0.5f, cy - h * 0.5f,
                                cx + w * 0.5f, cy + h * 0.5f);
    g_cls   [row] = (unsigned char)(bc - 1);
}

// ---------------------------------------------------------------------------
// 64-bit key: [monotone score bits:32][~orig_idx:16][class-sorted pos:16]
// unsigned MAX == (score desc, orig_idx asc); pos rides along for lookups.
// Key 0 == suppressed/empty.
// ---------------------------------------------------------------------------
__device__ __forceinline__ unsigned long long
pack_key(float v, unsigned int oidx, unsigned int gpos) {
    unsigned int b = __float_as_uint(v);
    b ^= (unsigned int)(((int)b >> 31) | 0x80000000);
    return ((unsigned long long)b << 32) |
           ((unsigned long long)((~oidx) & 0xFFFFu) << 16) |
           (unsigned long long)gpos;
}

// ---------------------------------------------------------------------------
// Stage 2: one CTA per batch.
//   Phase A (1024 thr): counting sort by class into smem (boxes + keys).
//   Phase B (20 warps): initial per-class head (max active key).
//   Phase C (warp 0)  : 200-step lazy selection loop, NO barriers:
//       winner = max over 20 class heads; emit; one fused sweep of the
//       winner's class wipes IoU>0.45 entries and recomputes that head.
//   Phase D (1024 thr): zero-fill remaining rows.
// ---------------------------------------------------------------------------
// smem: sbox NP*16 | skey NP*8 | hist/cstart/heads/s_t tail
#define SMEM_BYTES (NP * 16 + NP * 8 + 1024)

__global__ __launch_bounds__(NT, 1)
void nms_kernel(float* __restrict__ out) {
    extern __shared__ unsigned char smem_raw[];
    float4*             sbox  = (float4*)smem_raw;                   // NP
    unsigned long long* skey  = (unsigned long long*)(sbox + NP);    // NP
    unsigned char*      tail  = (unsigned char*)(skey + NP);
    int*                hist   = (int*)tail;                         // 32
    int*                cstart = hist + 32;                          // 21 used
    unsigned long long* heads  = (unsigned long long*)(tail + 256);  // 20 used
    int*                s_t    = (int*)(tail + 512);

    const int b    = blockIdx.x;
    const int tid  = threadIdx.x;
    const int wid  = tid >> 5;
    const int lane = tid & 31;
    const size_t base = (size_t)b * NP;
    const unsigned int full = 0xffffffffu;

    // ---- Phase A: counting sort by class ----
    if (tid < 32) hist[tid] = 0;
    __syncthreads();

    unsigned char oc[9];
#pragma unroll
    for (int i = 0; i < 9; i++) {
        int e = tid + i * NT;
        if (e < NP) {
            oc[i] = g_cls[base + e];
            atomicAdd(&hist[oc[i]], 1);
        }
    }
    __syncthreads();
    if (tid == 0) {
        int run = 0;
#pragma unroll
        for (int c = 0; c < 20; c++) { cstart[c] = run; run += hist[c]; }
        cstart[20] = run;   // == NP
    }
    __syncthreads();
    if (tid < 20) hist[tid] = cstart[tid];   // running counters
    __syncthreads();
#pragma unroll
    for (int i = 0; i < 9; i++) {
        int e = tid + i * NT;
        if (e < NP) {
            int pos = atomicAdd(&hist[oc[i]], 1);
            sbox[pos] = g_boxes[base + e];
            skey[pos] = pack_key(g_scores[base + e], (unsigned)e, (unsigned)pos);
        }
    }
    __syncthreads();

    // ---- Phase B: initial per-class heads (warps 0..19) ----
    if (wid < 20) {
        int st = cstart[wid], en = cstart[wid + 1];
        unsigned long long m = 0;
        for (int e = st + lane; e < en; e += 32) {
            unsigned long long k = skey[e];
            if (k > m) m = k;
        }
#pragma unroll
        for (int o = 16; o > 0; o >>= 1) {
            unsigned long long ok = __shfl_xor_sync(full, m, o);
            if (ok > m) m = ok;
        }
        if (lane == 0) heads[wid] = m;
    }
    __syncthreads();

    float* orow = out + (size_t)b * (TOPK * 6);

    // ---- Phase C: warp 0 runs the selection loop, others park at barrier ----
    if (wid == 0) {
        unsigned long long h = (lane < 20) ? heads[lane] : 0ull;
        int cs = (lane <= 20) ? cstart[lane] : 0;
        int t = 0;
        for (; t < TOPK; t++) {
            // global max over class heads
            unsigned long long hl = h, m = h;
#pragma unroll
            for (int o = 16; o > 0; o >>= 1) {
                unsigned long long ok = __shfl_xor_sync(full, m, o);
                if (ok > m) m = ok;
            }
            unsigned int hb = (unsigned int)(m >> 32);
            if (hb <= 0x80000000u) break;   // best score <= 0 -> zero rows

            int cstar = __ffs(__ballot_sync(full, hl == m)) - 1;
            int gpos  = (int)(m & 0xFFFFu);
            float4 bbx = sbox[gpos];        // uniform LDS broadcast
            float  bar = (bbx.z - bbx.x) * (bbx.w - bbx.y);

            if (lane == 0) {
                orow[t * 6 + 0] = bbx.x;
                orow[t * 6 + 1] = bbx.y;
                orow[t * 6 + 2] = bbx.z;
                orow[t * 6 + 3] = bbx.w;
                orow[t * 6 + 4] = __uint_as_float(hb ^ 0x80000000u);
                orow[t * 6 + 5] = (float)cstar;
            }

            int st = __shfl_sync(full, cs, cstar);
            int en = __shfl_sync(full, cs, cstar + 1);

            // fused suppress + head-recompute sweep over the winner class
            unsigned long long nm = 0;
            for (int e = st + lane; e < en; e += 32) {
                unsigned long long k = skey[e];
                if (k) {
                    float4 bx = sbox[e];
                    float ix1 = fmaxf(bbx.x, bx.x);
                    float iy1 = fmaxf(bbx.y, bx.y);
                    float ix2 = fminf(bbx.z, bx.z);
                    float iy2 = fminf(bbx.w, bx.w);
                    float inter = fmaxf(ix2 - ix1, 0.0f) * fmaxf(iy2 - iy1, 0.0f);
                    float ar = (bx.z - bx.x) * (bx.w - bx.y);
                    float iou = inter / (bar + ar - inter);
                    if (iou > 0.45f) skey[e] = 0ull;   // selected wipes itself too
                    else if (k > nm) nm = k;
                }
            }
#pragma unroll
            for (int o = 16; o > 0; o >>= 1) {
                unsigned long long ok = __shfl_xor_sync(full, nm, o);
                if (ok > nm) nm = ok;
            }
            if (lane == cstar) h = nm;
        }
        if (lane == 0) *s_t = t;
    }
    __syncthreads();

    // ---- Phase D: zero-fill remaining rows (d_out is poisoned) ----
    int tdone = *s_t;
    for (int i = tdone * 6 + tid; i < TOPK * 6; i += NT) orow[i] = 0.0f;
}

// ---------------------------------------------------------------------------
extern "C" void kernel_launch(void* const* d_in, const int* in_sizes, int n_in,
                              void* d_out, int out_size) {
    const float* loc   = (const float*)d_in[0];
    const float* conf  = (const float*)d_in[1];
    const float* prior = (const float*)d_in[2];
    float* out = (float*)d_out;

    cudaFuncSetAttribute(nms_kernel,
                         cudaFuncAttributeMaxDynamicSharedMemorySize,
                         SMEM_BYTES);

    preprocess_kernel<<<(NB * NP + 255) / 256, 256>>>(loc, conf, prior);
    nms_kernel<<<NB, NT, SMEM_BYTES>>>(out);
}

// round 5
// speedup vs baseline: 5.6287x; 5.6287x over previous
#include <cuda_runtime.h>
#include <cstdint>
#include <cfloat>

typedef unsigned long long ull;

// Problem constants
#define NB   128
#define NP   8732
#define NC   21
#define TOPK 200
#define NT   1024

// Algorithm config
#define HB     8192      // histogram bins (13-bit digit)
#define CHCAP  4096      // gathered-chunk capacity (keys)
#define CCAP   48        // per-class accepted-list capacity
#define OCAP   200       // overflow accepted capacity (exactness fallback)

// Global scratch (no allocation allowed)
__device__ float4 g_boxes[NB * NP];

// key = [monotone score bits:32][~idx:16][cls:8][0:8]
// unsigned compare == (score desc, idx asc); cls rides along (never affects
// order: keys are unique in the top 48 bits because idx is unique).
__device__ __forceinline__ ull pack_key(float v, unsigned idx, unsigned cls) {
    unsigned bq = __float_as_uint(v);
    bq ^= (unsigned)(((int)bq >> 31) | 0x80000000);
    return ((ull)bq << 32) | ((ull)((~idx) & 0xFFFFu) << 16) | ((ull)cls << 8);
}

// smem layout sizes (bytes)
#define SM_CLIST   (20 * CCAP * 16)        // 15360
#define SM_OBOX    (OCAP * 16)             // 3200
#define SM_PBOX    (32 * 16)               // 512
#define SM_SKEY    (NP * 8)                // 69856
#define SM_CHUNK   (CHCAP * 8)             // 32768
#define SM_HIST    (HB * 4)                // 32768
#define SM_INTS    ((20 + OCAP + 16) * 4)  // 944
#define SMEM_BYTES (SM_CLIST + SM_OBOX + SM_PBOX + SM_SKEY + SM_CHUNK + SM_HIST + SM_INTS + 64)

__global__ __launch_bounds__(NT, 1)
void detect_kernel(const float* __restrict__ loc,
                   const float* __restrict__ conf,
                   const float* __restrict__ prior,
                   float* __restrict__ out) {
    extern __shared__ unsigned char smem_raw[];
    float4* clist = (float4*)smem_raw;                      // 20*CCAP
    float4* obox  = clist + 20 * CCAP;                      // OCAP
    float4* pbox  = obox + OCAP;                            // 32
    ull*    skey  = (ull*)(pbox + 32);                      // NP
    ull*    chunk = skey + NP;                              // CHCAP
    int*    hist  = (int*)(chunk + CHCAP);                  // HB
    int*    ccount = hist + HB;                             // 20
    int*    ocls   = ccount + 20;                           // OCAP
    int*    sc     = ocls + OCAP;                           // scalars
    // sc[0]=T  sc[1]=nout  sc[2]=done  sc[4]=ocount  sc[5]=S_level
    // sc[6]=Aab  sc[7]=gather counter  sc[8]=allrem flag
    ull*    slimit = (ull*)(sc + 12);                       // limitkey (8B aligned)

    const int b    = blockIdx.x;
    const int tid  = threadIdx.x;
    const int wid  = tid >> 5;
    const int lane = tid & 31;
    const size_t base = (size_t)b * NP;
    const unsigned full = 0xffffffffu;

    // ================= Phase 0: score + decode, build keys =================
    for (int i = 0; i < 9; i++) {
        int e = tid + i * NT;
        if (e < NP) {
            const float* cp = conf + (base + e) * NC;
            float c[NC];
#pragma unroll
            for (int q = 0; q < NC; q++) c[q] = cp[q];
            float m = c[0];
#pragma unroll
            for (int q = 1; q < NC; q++) m = fmaxf(m, c[q]);
            float sum = 0.0f;
#pragma unroll
            for (int q = 0; q < NC; q++) sum += expf(c[q] - m);
            float bm = c[1]; int bc = 1;
#pragma unroll
            for (int q = 2; q < NC; q++) {
                if (c[q] > bm) { bm = c[q]; bc = q; }
            }
            float score = expf(bm - m) / sum;
            float ms = (score > 0.01f) ? score : -1.0f;

            float4 l  = ((const float4*)loc)[base + e];
            float4 pr = ((const float4*)prior)[e];
            float cx = pr.x + l.x * 0.1f * pr.z;
            float cy = pr.y + l.y * 0.1f * pr.w;
            float w  = pr.z * expf(l.z * 0.2f);
            float h  = pr.w * expf(l.w * 0.2f);
            g_boxes[base + e] = make_float4(cx - w * 0.5f, cy - h * 0.5f,
                                            cx + w * 0.5f, cy + h * 0.5f);
            skey[e] = pack_key(ms, (unsigned)e, (unsigned)(bc - 1));
        }
    }
    if (tid < 20) ccount[tid] = 0;
    if (tid == 0) { sc[1] = 0; sc[2] = 0; sc[4] = 0; *slimit = ~0ull; }
    __syncthreads();

    // ================= Refill rounds =================
    for (int round = 0; round < 64; round++) {
        ull limitkey = *slimit;
        int nout0 = sc[1];
        int want0 = (TOPK - nout0) + ((round == 0) ? 184 : 128);

        // ---- exact-enough threshold select (refine only if fat bins) ----
        ull lo = 0, thk = 0;
        int Aglob = 0, Stotal = 0, allrem = 0;
        for (int shift = 51; ; shift -= 13) {
            for (int q = tid; q < HB; q += NT) hist[q] = 0;
            __syncthreads();
            bool lvl1 = (shift == 51);
            ull hi = lvl1 ? ~0ull : (lo + (1ull << (shift + 13)));
            for (int i = 0; i < 9; i++) {
                int e = tid + i * NT;
                if (e < NP) {
                    ull k = skey[e];
                    if (k < limitkey && (lvl1 || (k >= lo && k < hi)))
                        atomicAdd(&hist[(int)((k >> shift) & 0x1FFF)], 1);
                }
            }
            __syncthreads();
            int wantl = want0 - Aglob;
            if (wid == 0) {
                int gs = 0;
                for (int q = 0; q < 256; q++) gs += hist[lane * 256 + q];
                int suf = gs;
#pragma unroll
                for (int o = 1; o < 32; o <<= 1) {
                    int t2 = __shfl_down_sync(full, suf, o);
                    if (lane + o < 32) suf += t2;
                }
                unsigned mk = __ballot_sync(full, suf >= wantl);
                if (mk == 0) {
                    if (lane == 0) { sc[8] = 1; sc[5] = suf; sc[0] = 0; sc[6] = 0; }
                } else {
                    int G = 31 - __clz(mk);
                    int sufn = __shfl_down_sync(full, suf, 1);
                    int ab = (G < 31) ? sufn : 0;
                    int above = __shfl_sync(full, ab, G);
                    if (lane == 0) {
                        int acc = above, T = G * 256, Aab = above, Slev = above;
                        for (int bn = G * 256 + 255; bn >= G * 256; bn--) {
                            int hh = hist[bn];
                            if (acc + hh >= wantl) { T = bn; Aab = acc; Slev = acc + hh; break; }
                            acc += hh;
                        }
                        sc[8] = 0; sc[0] = T; sc[5] = Slev; sc[6] = Aab;
                    }
                }
            }
            __syncthreads();
            if (sc[8]) {  // fewer than want remain: take everything below limit
                allrem = 1; thk = lo; Stotal = Aglob + sc[5]; break;
            }
            int T = sc[0];
            thk = lo | ((ull)T << shift);
            Stotal = Aglob + sc[5];
            if (Stotal <= CHCAP || shift <= 12) break;
            Aglob += sc[6];
            lo = thk;
            __syncthreads();
        }

        // ---- gather ----
        if (tid == 0) sc[7] = 0;
        __syncthreads();
        for (int i = 0; i < 9; i++) {
            int e = tid + i * NT;
            if (e < NP) {
                ull k = skey[e];
                if (k < limitkey && k >= thk) {
                    int pos = atomicAdd(&sc[7], 1);
                    if (pos < CHCAP) chunk[pos] = k;
                }
            }
        }
        __syncthreads();
        int Sg = sc[7]; if (Sg > CHCAP) Sg = CHCAP;
        int P2 = 32; while (P2 < Sg) P2 <<= 1;
        for (int q = Sg + tid; q < P2; q += NT) chunk[q] = 0ull;
        __syncthreads();

        // ---- bitonic sort descending (P2 <= 4096) ----
        for (int kk = 2; kk <= P2; kk <<= 1) {
            for (int j = kk >> 1; j > 0; j >>= 1) {
                for (int p = tid; p < (P2 >> 1); p += NT) {
                    int lowb = p & (j - 1);
                    int i1 = ((p ^ lowb) << 1) | lowb;
                    int i2 = i1 | j;
                    ull a = chunk[i1], c2 = chunk[i2];
                    bool desc = ((i1 & kk) == 0);
                    if (desc ? (a < c2) : (a > c2)) { chunk[i1] = c2; chunk[i2] = a; }
                }
                __syncthreads();
            }
        }

        // ---- greedy walk (warp 0 only) ----
        if (wid == 0) {
            int nout = sc[1];
            int done = 0;
            int ocnt = sc[4];
            for (int bpos = 0; bpos < Sg && nout < TOPK && !done; bpos += 32) {
                int mrem = Sg - bpos; if (mrem > 32) mrem = 32;
                // prefetch boxes for the next 32 sorted candidates
                ull kp = (lane < mrem) ? chunk[bpos + lane] : 0ull;
                unsigned hbp = (unsigned)(kp >> 32);
                if (hbp > 0x80000000u) {
                    int idx = (int)((~(unsigned)(kp >> 16)) & 0xFFFFu);
                    pbox[lane] = g_boxes[base + idx];
                }
                __syncwarp();
                for (int r = 0; r < mrem; r++) {
                    ull kr = chunk[bpos + r];                 // uniform LDS
                    unsigned hbr = (unsigned)(kr >> 32);
                    if (hbr <= 0x80000000u) { done = 1; break; }
                    int cr = (int)((kr >> 8) & 0xFF);
                    float4 cb = pbox[r];
                    float car = (cb.z - cb.x) * (cb.w - cb.y);
                    int nc = ccount[cr];
                    bool hit = false;
                    for (int q0 = 0; q0 < nc; q0 += 32) {
                        int q = q0 + lane;
                        if (q < nc) {
                            float4 ab = clist[cr * CCAP + q];
                            float ix1 = fmaxf(cb.x, ab.x);
                            float iy1 = fmaxf(cb.y, ab.y);
                            float ix2 = fminf(cb.z, ab.z);
                            float iy2 = fminf(cb.w, ab.w);
                            float inter = fmaxf(ix2 - ix1, 0.0f) * fmaxf(iy2 - iy1, 0.0f);
                            float ar = (ab.z - ab.x) * (ab.w - ab.y);
                            if (inter / (car + ar - inter) > 0.45f) hit = true;
                        }
                    }
                    for (int q0 = 0; q0 < ocnt; q0 += 32) {    // overflow (normally 0)
                        int q = q0 + lane;
                        if (q < ocnt && ocls[q] == cr) {
                            float4 ab = obox[q];
                            float ix1 = fmaxf(cb.x, ab.x);
                            float iy1 = fmaxf(cb.y, ab.y);
                            float ix2 = fminf(cb.z, ab.z);
                            float iy2 = fminf(cb.w, ab.w);
                            float inter = fmaxf(ix2 - ix1, 0.0f) * fmaxf(iy2 - iy1, 0.0f);
                            float ar = (ab.z - ab.x) * (ab.w - ab.y);
                            if (inter / (car + ar - inter) > 0.45f) hit = true;
                        }
                    }
                    if (!__any_sync(full, hit)) {
                        bool ovf = (nc >= CCAP);
                        if (lane == 0) {
                            float* orow = out + (size_t)b * (TOPK * 6) + nout * 6;
                            orow[0] = cb.x; orow[1] = cb.y;
                            orow[2] = cb.z; orow[3] = cb.w;
                            orow[4] = __uint_as_float(hbr ^ 0x80000000u);
                            orow[5] = (float)cr;
                            if (!ovf) { clist[cr * CCAP + nc] = cb; ccount[cr] = nc + 1; }
                            else if (ocnt < OCAP) { obox[ocnt] = cb; ocls[ocnt] = cr; }
                        }
                        if (ovf) ocnt++;
                        nout++;
                        __syncwarp();
                        if (nout == TOPK) break;
                    }
                }
            }
            if (lane == 0) { sc[1] = nout; sc[2] = done; sc[4] = ocnt; }
        }
        __syncthreads();

        if (sc[1] >= TOPK || sc[2] || allrem || thk == 0) break;
        if (tid == 0) *slimit = thk;
        __syncthreads();
    }

    // ================= zero-fill remaining rows =================
    int nout = sc[1];
    float* orow = out + (size_t)b * (TOPK * 6);
    for (int q = nout * 6 + tid; q < TOPK * 6; q += NT) orow[q] = 0.0f;
}

// ---------------------------------------------------------------------------
extern "C" void kernel_launch(void* const* d_in, const int* in_sizes, int n_in,
                              void* d_out, int out_size) {
    const float* loc   = (const float*)d_in[0];
    const float* conf  = (const float*)d_in[1];
    const float* prior = (const float*)d_in[2];
    float* out = (float*)d_out;

    cudaFuncSetAttribute(detect_kernel,
                         cudaFuncAttributeMaxDynamicSharedMemorySize,
                         SMEM_BYTES);

    detect_kernel<<<NB, NT, SMEM_BYTES>>>(loc, conf, prior, out);
}

// round 6
// speedup vs baseline: 7.2492x; 1.2879x over previous
#include <cuda_runtime.h>
#include <cstdint>
#include <cfloat>

typedef unsigned long long ull;

// Problem constants
#define NB   128
#define NP   8732
#define NC   21
#define TOPK 200
#define NT   1024

// Select/sort config
#define BIN0  6016          // coarse bin of smallest score > 0.01 is 6020; <1.0 -> 6127
#define NBIN  128
#define CHCAP 1024
#define CCAP  48
#define OCAP  200

// Global scratch (no allocation allowed)
__device__ float4 g_boxes[NB * NP];

// smem byte offsets. Region U (0..87040) is the phase-0 staging buffer and is
// reused afterwards by whist/ghist/hist2/chunks/clist/obox/ocls (53.9KB used).
#define OFF_WHIST  0          // int[32][128]   16384
#define OFF_GHIST  16384      // int[128]         512
#define OFF_HIST2  16896      // int[256]        1024
#define OFF_CHA    17920      // ull[1024]       8192
#define OFF_CHB    26112      // ull[1024]       8192
#define OFF_CLIST  34304      // float4[20*48]  15360
#define OFF_OBOX   49664      // float4[200]     3200
#define OFF_OCLS   52864      // int[200]         800
#define U_SIZE     87040      // float stage[32][680]
#define OFF_SKEY   87040      // ull[8732]      69856
#define OFF_SC     156896     // int[64]: 0..15 scalars, 16..47 ccount; +192 slimit
#define SMEM_BYTES (156896 + 256 + 16)

// key = [monotone score:32][~idx:16][cls:8][0:8]; unsigned MAX == (score desc, idx asc)
__device__ __forceinline__ ull pack_key(float v, unsigned idx, unsigned cls) {
    unsigned bq = __float_as_uint(v);
    bq ^= (unsigned)(((int)bq >> 31) | 0x80000000);
    return ((ull)bq << 32) | ((ull)((~idx) & 0xFFFFu) << 16) | ((ull)cls << 8);
}

__global__ __launch_bounds__(NT, 1)
void detect_kernel(const float* __restrict__ loc,
                   const float* __restrict__ conf,
                   const float* __restrict__ prior,
                   float* __restrict__ out) {
    extern __shared__ unsigned char smem_raw[];
    ull*    skey   = (ull*)(smem_raw + OFF_SKEY);
    int*    sc     = (int*)(smem_raw + OFF_SC);
    int*    ccount = sc + 16;
    ull*    slimit = (ull*)(smem_raw + OFF_SC + 192);
    int*    ghist  = (int*)(smem_raw + OFF_GHIST);
    int*    hist2  = (int*)(smem_raw + OFF_HIST2);
    ull*    chA    = (ull*)(smem_raw + OFF_CHA);
    ull*    chB    = (ull*)(smem_raw + OFF_CHB);
    float4* clist  = (float4*)(smem_raw + OFF_CLIST);
    float4* obox   = (float4*)(smem_raw + OFF_OBOX);
    int*    ocls   = (int*)(smem_raw + OFF_OCLS);

    const int b    = blockIdx.x;
    const int tid  = threadIdx.x;
    const int wid  = tid >> 5;
    const int lane = tid & 31;
    const size_t base = (size_t)b * NP;
    const unsigned full = 0xffffffffu;
    float* outb = out + (size_t)b * (TOPK * 6);

    // ================ Phase 0: staged conf loads -> keys + boxes ================
    {
        float* stage = (float*)smem_raw + wid * 680;   // 672 floats used
        const float* confb = conf + base * NC;
        for (int i = 0; i < 9; i++) {
            int brow = i * NT + wid * 32;
            if (brow < NP) {
                int nrows = NP - brow; if (nrows > 32) nrows = 32;
                int nflt = nrows * NC;
                const float* src = confb + (size_t)brow * NC;
#pragma unroll
                for (int q = 0; q < NC; q++) {
                    int o = q * 32 + lane;
                    if (o < nflt) stage[o] = src[o];
                }
                __syncwarp();
                if (lane < nrows) {
                    int e = brow + lane;
                    float c[NC];
#pragma unroll
                    for (int q = 0; q < NC; q++) c[q] = stage[lane * NC + q];
                    float m = c[0];
#pragma unroll
                    for (int q = 1; q < NC; q++) m = fmaxf(m, c[q]);
                    float sum = 0.0f;
#pragma unroll
                    for (int q = 0; q < NC; q++) sum += expf(c[q] - m);
                    float bm = c[1]; int bc = 1;
#pragma unroll
                    for (int q = 2; q < NC; q++) {
                        if (c[q] > bm) { bm = c[q]; bc = q; }
                    }
                    float score = expf(bm - m) / sum;
                    float ms = (score > 0.01f) ? score : -1.0f;

                    float4 l  = ((const float4*)loc)[base + e];
                    float4 pr = ((const float4*)prior)[e];
                    float cx = pr.x + l.x * 0.1f * pr.z;
                    float cy = pr.y + l.y * 0.1f * pr.w;
                    float w  = pr.z * expf(l.z * 0.2f);
                    float h  = pr.w * expf(l.w * 0.2f);
                    g_boxes[base + e] = make_float4(cx - w * 0.5f, cy - h * 0.5f,
                                                    cx + w * 0.5f, cy + h * 0.5f);
                    skey[e] = pack_key(ms, (unsigned)e, (unsigned)(bc - 1));
                }
                __syncwarp();
            }
        }
    }
    if (tid < 32) ccount[tid] = 0;
    if (tid == 0) { sc[1] = 0; sc[2] = 0; sc[4] = 0; *slimit = ~0ull; }
    __syncthreads();

    // ================ Refill rounds (normally 1) ================
    for (int round = 0; round < 32; round++) {
        ull limit = *slimit;
        int want = TOPK - sc[1] + 184;

        // ---- per-warp 128-bin histogram (match-aggregated, no atomics) ----
        int* whist = (int*)(smem_raw + OFF_WHIST) + wid * NBIN;
        for (int q = lane; q < NBIN; q += 32) whist[q] = 0;
        __syncwarp();
        for (int i = 0; i < 9; i++) {
            int e = tid + i * NT;
            ull k = (e < NP) ? skey[e] : 0ull;
            int bin = (int)(k >> 51) - BIN0;
            bool val = (e < NP) && (k < limit) && (bin >= 0) && (bin < NBIN);
            int mbin = val ? bin : -1;
            unsigned mm = __match_any_sync(full, mbin);
            if (val && lane == (__ffs(mm) - 1)) whist[mbin] += __popc(mm);
        }
        __syncthreads();
        if (tid < NBIN) {
            int acc = 0;
            int* wh = (int*)(smem_raw + OFF_WHIST);
#pragma unroll
            for (int w = 0; w < 32; w++) acc += wh[w * NBIN + tid];
            ghist[tid] = acc;
        }
        __syncthreads();

        // ---- parallel suffix-scan threshold select (warp 0) ----
        if (wid == 0) {
            if (lane == 0) { sc[0] = 0; sc[3] = 0; sc[5] = 0; sc[6] = 0; sc[7] = 0; sc[9] = 0; }
            __syncwarp();
            int c0 = ghist[lane * 4], c1 = ghist[lane * 4 + 1];
            int c2 = ghist[lane * 4 + 2], c3 = ghist[lane * 4 + 3];
            int s = c0 + c1 + c2 + c3;
            int suf = s;
#pragma unroll
            for (int o = 1; o < 32; o <<= 1) {
                int tt = __shfl_down_sync(full, suf, o);
                if (lane + o < 32) suf += tt;
            }
            int total = __shfl_sync(full, suf, 0);
            int cum = suf - s;   // bins in higher lanes
            int T = -1, A = 0, S = 0;
            if (cum < want && cum + c3 >= want) { T = lane * 4 + 3; A = cum; S = cum + c3; }
            cum += c3;
            if (T < 0 && cum < want && cum + c2 >= want) { T = lane * 4 + 2; A = cum; S = cum + c2; }
            cum += c2;
            if (T < 0 && cum < want && cum + c1 >= want) { T = lane * 4 + 1; A = cum; S = cum + c1; }
            cum += c1;
            if (T < 0 && cum < want && cum + c0 >= want) { T = lane * 4;     A = cum; S = cum + c0; }
            if (T >= 0) { sc[0] = T; sc[3] = A; sc[5] = S; }
            if (lane == 0 && total < want) { sc[6] = 1; sc[0] = 0; sc[3] = 0; sc[5] = total; }
        }
        __syncthreads();

        // ---- optional 8-bit refinement if the boundary bin is fat ----
        if (sc[5] > CHCAP && !sc[6]) {
            if (tid < 256) hist2[tid] = 0;
            __syncthreads();
            int Tc = BIN0 + sc[0];
            for (int i = 0; i < 9; i++) {
                int e = tid + i * NT;
                if (e < NP) {
                    ull k = skey[e];
                    if (k < limit && (int)(k >> 51) == Tc)
                        atomicAdd(&hist2[(int)((k >> 43) & 0xFF)], 1);
                }
            }
            __syncthreads();
            if (wid == 0) {
                int cc[8], s = 0;
#pragma unroll
                for (int q = 0; q < 8; q++) { cc[q] = hist2[lane * 8 + q]; s += cc[q]; }
                int suf = s;
#pragma unroll
                for (int o = 1; o < 32; o <<= 1) {
                    int tt = __shfl_down_sync(full, suf, o);
                    if (lane + o < 32) suf += tt;
                }
                int want2 = want - sc[3];
                int cum = suf - s;
                int T2 = -1;
#pragma unroll
                for (int q = 7; q >= 0; q--) {
                    if (T2 < 0 && cum < want2 && cum + cc[q] >= want2) T2 = lane * 8 + q;
                    cum += cc[q];
                }
                if (T2 >= 0) { sc[8] = T2; sc[9] = 1; }
            }
            __syncthreads();
        }
        ull thk = ((ull)(BIN0 + sc[0]) << 51);
        if (sc[9]) thk |= ((ull)sc[8] << 43);

        // ---- warp-aggregated gather of candidates ----
        for (int i = 0; i < 9; i++) {
            int e = tid + i * NT;
            ull k = (e < NP) ? skey[e] : 0ull;
            bool cnd = (k >= thk) && (k < limit);
            unsigned mm = __ballot_sync(full, cnd);
            int cnt = __popc(mm);
            int bp = 0;
            if (lane == 0 && cnt) bp = atomicAdd(&sc[7], cnt);
            bp = __shfl_sync(full, bp, 0);
            if (cnd) {
                int pos = bp + __popc(mm & ((1u << lane) - 1u));
                if (pos < CHCAP) chA[pos] = k;
            }
        }
        __syncthreads();
        int Sg = sc[7]; if (Sg > CHCAP) Sg = CHCAP;

        // ---- hybrid bitonic sort (1024 keys, descending) ----
        {
            ull v = (tid < Sg) ? chA[tid] : 0ull;
            ull* bufs[2] = { chA, chB };
            int pb = 0;
            for (int k = 2; k <= 1024; k <<= 1) {
                int j = k >> 1;
                for (; j >= 32; j >>= 1) {         // cross-warp: ping-pong, 1 barrier
                    bufs[pb][tid] = v;
                    __syncthreads();
                    ull o = bufs[pb][tid ^ j];
                    pb ^= 1;
                    bool keepmax = ((tid & k) == 0) == ((tid & j) == 0);
                    bool gt = v > o;
                    v = keepmax ? (gt ? v : o) : (gt ? o : v);
                }
                for (; j > 0; j >>= 1) {           // in-warp: shfl, no barrier
                    ull o = __shfl_xor_sync(full, v, j);
                    bool keepmax = ((tid & k) == 0) == ((tid & j) == 0);
                    bool gt = v > o;
                    v = keepmax ? (gt ? v : o) : (gt ? o : v);
                }
            }
            chA[tid] = v;
        }
        __syncthreads();

        // ---- window-parallel greedy walk (warp 0) ----
        if (wid == 0) {
            int nout = sc[1];
            int done = 0;
            for (int w0 = 0; w0 < Sg && nout < TOPK && !done; w0 += 32) {
                int m = Sg - w0; if (m > 32) m = 32;
                ull k = (lane < m) ? chA[w0 + lane] : 0ull;
                unsigned hb = (unsigned)(k >> 32);
                bool valid = hb > 0x80000000u;
                unsigned validmask = __ballot_sync(full, valid);
                float4 cb = make_float4(0.f, 0.f, 0.f, 0.f);
                int cr = -1; float car = 0.f;
                if (valid) {
                    int idx = (int)((~(unsigned)(k >> 16)) & 0xFFFFu);
                    cr = (int)((k >> 8) & 0xFFu);
                    cb = g_boxes[base + idx];
                    car = (cb.z - cb.x) * (cb.w - cb.y);
                }
                // vs previously-accepted (per-class + overflow lists)
                bool hit = false;
                if (valid) {
                    int nc = ccount[cr]; if (nc > CCAP) nc = CCAP;
                    for (int q = 0; q < nc; q++) {
                        float4 ab = clist[cr * CCAP + q];
                        float ix1 = fmaxf(ab.x, cb.x), iy1 = fmaxf(ab.y, cb.y);
                        float ix2 = fminf(ab.z, cb.z), iy2 = fminf(ab.w, cb.w);
                        float inter = fmaxf(ix2 - ix1, 0.f) * fmaxf(iy2 - iy1, 0.f);
                        float ar = (ab.z - ab.x) * (ab.w - ab.y);
                        if (inter / (ar + car - inter) > 0.45f) hit = true;
                    }
                    int oc = sc[4]; if (oc > OCAP) oc = OCAP;
                    for (int q = 0; q < oc; q++) {
                        if (ocls[q] == cr) {
                            float4 ab = obox[q];
                            float ix1 = fmaxf(ab.x, cb.x), iy1 = fmaxf(ab.y, cb.y);
                            float ix2 = fminf(ab.z, cb.z), iy2 = fminf(ab.w, cb.w);
                            float inter = fmaxf(ix2 - ix1, 0.f) * fmaxf(iy2 - iy1, 0.f);
                            float ar = (ab.z - ab.x) * (ab.w - ab.y);
                            if (inter / (ar + car - inter) > 0.45f) hit = true;
                        }
                    }
                }
                unsigned priormask = __ballot_sync(full, hit);
                // pairwise within window
                unsigned supmask = 0;
                for (int rr = 0; rr < 32; rr++) {
                    float bx = __shfl_sync(full, cb.x, rr);
                    float by = __shfl_sync(full, cb.y, rr);
                    float bz = __shfl_sync(full, cb.z, rr);
                    float bw = __shfl_sync(full, cb.w, rr);
                    int   rc = __shfl_sync(full, cr, rr);
                    if (valid && rr < lane && rc == cr && ((validmask >> rr) & 1u)) {
                        float ix1 = fmaxf(bx, cb.x), iy1 = fmaxf(by, cb.y);
                        float ix2 = fminf(bz, cb.z), iy2 = fminf(bw, cb.w);
                        float inter = fmaxf(ix2 - ix1, 0.f) * fmaxf(iy2 - iy1, 0.f);
                        float ra = (bz - bx) * (bw - by);
                        if (inter / (ra + car - inter) > 0.45f) supmask |= 1u << rr;
                    }
                }
                // serial resolve in registers (uniform across lanes)
                unsigned accept = 0;
                for (int rr = 0; rr < 32; rr++) {
                    unsigned srr = __shfl_sync(full, supmask, rr);
                    unsigned bit = 1u << rr;
                    if ((validmask & bit) && !(priormask & bit) && !(srr & accept))
                        accept |= bit;
                }
                int rem = TOPK - nout;
                unsigned lmask = (1u << lane) - 1u;
                int rank = __popc(accept & lmask);
                if (((accept >> lane) & 1u) && rank < rem) {
                    int pos = nout + rank;
                    float* orow = outb + pos * 6;
                    orow[0] = cb.x; orow[1] = cb.y; orow[2] = cb.z; orow[3] = cb.w;
                    orow[4] = __uint_as_float(hb ^ 0x80000000u);
                    orow[5] = (float)cr;
                    int slot = atomicAdd(&ccount[cr], 1);
                    if (slot < CCAP) clist[cr * CCAP + slot] = cb;
                    else {
                        int os = atomicAdd(&sc[4], 1);
                        if (os < OCAP) { obox[os] = cb; ocls[os] = cr; }
                    }
                }
                __syncwarp();
                int na = __popc(accept); if (na > rem) na = rem;
                nout += na;
                unsigned expect = (m == 32) ? 0xFFFFFFFFu : ((1u << m) - 1u);
                if (validmask != expect) done = 1;
            }
            if (lane == 0) { sc[1] = nout; sc[2] = done; }
        }
        __syncthreads();

        if (sc[1] >= TOPK || sc[2] || sc[6] || Sg == 0) break;
        if (tid == 0) *slimit = thk;
        __syncthreads();
    }

    // ================ zero-fill remaining rows ================
    int nout = sc[1];
    for (int q = nout * 6 + tid; q < TOPK * 6; q += NT) outb[q] = 0.0f;
}

// ---------------------------------------------------------------------------
extern "C" void kernel_launch(void* const* d_in, const int* in_sizes, int n_in,
                              void* d_out, int out_size) {
    const float* loc   = (const float*)d_in[0];
    const float* conf  = (const float*)d_in[1];
    const float* prior = (const float*)d_in[2];
    float* out = (float*)d_out;

    cudaFuncSetAttribute(detect_kernel,
                         cudaFuncAttributeMaxDynamicSharedMemorySize,
                         SMEM_BYTES);

    detect_kernel<<<NB, NT, SMEM_BYTES>>>(loc, conf, prior, out);
}